// round 15
// baseline (speedup 1.0000x reference)
#include <cuda_runtime.h>
#include <cuda_bf16.h>

// LIF recurrent scan, v12: merged scan + RATE-LIMITED fill, parallel scatter.
//
// R14 evidence: full-rate fill (116 CTAs, ~5TB/s) saturates DRAM for its
// first ~26us and starves the scan's x-loads -> merged 176us (additive, no
// overlap win). v12 throttles the fill with __nanosleep between stripe-waves
// (~30% duty, ~1.4TB/s aggregate) so it hides entirely under the scan's
// ~128us. The scan needs only ~1TB/s; combined ~2.4TB/s << 8TB/s.
// Scatter was serial (1 block, 23.6us) -> now 1 block per row (~3us).
//
// Scan (unchanged v11/v7 core): 1 CTA/row, 1024 threads, 1 neuron/thread,
// state in registers for all T. CHUNK=10 speculative steps (no act, no
// stores, no barriers) + register fmaxf detector; mis-speculation -> exact
// replay with per-step barriers (rare). Next chunk's x prefetched into
// compile-time-bound registers (MLP=10). Scan never writes `out`: spikes
// (~200 total) append to per-CTA __device__ record buffers; rollback
// restores the smem record-count snapshot.

#define N_NEU     1024
#define THREADS   1024
#define CHUNK     10          // even; T=1000 = 100 chunks
#define FILL_CTAS 116
#define MAX_B     32
#define REC_CAP   4096

__device__ int   g_cnt[MAX_B];
__device__ int   g_pos[MAX_B][REC_CAP];   // t*N + n
__device__ float g_val[MAX_B][REC_CAP];

__device__ __forceinline__ float rank_k(const int* __restrict__ idx,
                                        const float* __restrict__ val,
                                        int c, float rec,
                                        const float* __restrict__ wrow) {
    for (int k = 0; k < c; k++)
        rec = fmaf(val[k], wrow[idx[k]], rec);
    return rec;
}

__device__ __forceinline__ void do_chunk(
    int tc, int T,
    float (&xcur)[CHUNK], float (&xnxt)[CHUNK],   // compile-time bound: regs
    float& state, float brec,
    const float* __restrict__ wrow,
    const float* __restrict__ xb,
    int* __restrict__ rpos, float* __restrict__ rval,   // this row's records
    int tid,
    int (&s_idx)[2][N_NEU], float (&s_val)[2][N_NEU],
    int (&s_cnt)[2], int& s_flag, int& s_rc,
    int& pb, int& qb)
{
    const float ALPHA = 0.9f;
    const float OMA   = 1.0f - 0.9f;

    const int c_prev  = s_cnt[pb];     // uniform; stable since last barriers
    const int rc_snap = s_rc;

    // ---- prefetch next chunk: clamped base + immediate offsets (MLP=10) ----
    {
        const float* xp = xb + (size_t)min(tc + CHUNK, T - CHUNK) * N_NEU;
#pragma unroll
        for (int s = 0; s < CHUNK; s++)
            xnxt[s] = xp[s * N_NEU];
    }

    const float snap = state;
    float mx = 0.0f;

    // -------- fast speculative pass: no stores, no barriers, no act --------
#pragma unroll
    for (int s = 0; s < CHUNK - 1; s++) {
        float rec = brec;
        if (s == 0)                            // compile-time branch
            rec = rank_k(s_idx[pb], s_val[pb], c_prev, brec, wrow);

        mx = fmaxf(mx, state);                 // detector: 1 FMNMX/step

        const float tot = xcur[s] + rec;
        state = (state - 0.0f) * ALPHA + OMA * tot;
    }

    // ---- last step of chunk: exact act (its spikes feed the next chunk) ----
    {
        const float sv  = state;
        const float act = (sv > 0.0f) ? floorf(sv) : 0.0f;
        if (act != 0.0f) {                     // rare: list push + record
            const int p = atomicAdd(&s_cnt[qb], 1);
            s_idx[qb][p] = tid;
            s_val[qb][p] = act;
            const int r = atomicAdd(&s_rc, 1) & (REC_CAP - 1);
            rpos[r] = (tc + CHUNK - 1) * N_NEU + tid;
            rval[r] = act;
        }
        const float tot = xcur[CHUNK - 1] + brec;   // rec = bias for s > 0
        state = (sv - act) * ALPHA + OMA * tot;
    }

    if (mx >= 1.0f) s_flag = 1;                // one STS per chunk, rare

    __syncthreads();                    // B1: flag & pushes visible
    const int f = s_flag;
    if (tid == 0 && !f) s_cnt[pb] = 0;  // retire prev list (commit only)
    __syncthreads();                    // B2: flag consumed by all

    if (f) {
        // -------- rollback: exact replay with per-step barriers --------
        state = snap;
        if (tid == 0) { s_cnt[qb] = 0; s_flag = 0; s_rc = rc_snap; }
        __syncthreads();

        int rb = pb, wb = qb;
#pragma unroll 1
        for (int s = 0; s < CHUNK; s++) {
            const int c = s_cnt[rb];
            const float rec = rank_k(s_idx[rb], s_val[rb], c, brec, wrow);

            const float sv  = state;
            const float act = (sv > 0.0f) ? floorf(sv) : 0.0f;
            if (act != 0.0f) {
                const int p = atomicAdd(&s_cnt[wb], 1);
                s_idx[wb][p] = tid;
                s_val[wb][p] = act;
                const int r = atomicAdd(&s_rc, 1) & (REC_CAP - 1);
                rpos[r] = (tc + s) * N_NEU + tid;
                rval[r] = act;
            }

            const float tot = xcur[s] + rec;
            state = (sv - act) * ALPHA + OMA * tot;

            __syncthreads();
            if (tid == 0) s_cnt[rb] = 0;
            __syncthreads();
            const int tmp = rb; rb = wb; wb = tmp;
        }
        pb = rb; qb = wb;   // CHUNK even: last-step spikes in pb, qb zeroed
    } else {
        const int tmp = pb; pb = qb; qb = tmp;
    }
}

__global__ __launch_bounds__(THREADS, 1)
void lif_merged_kernel(const float* __restrict__ x,     // [B, T, N]
                       const float* __restrict__ W,     // [N, N] (out, in)
                       const float* __restrict__ bias,  // [N]
                       float* __restrict__ out,         // [B, T, N]
                       int T, int B)
{
    const int tid = threadIdx.x;

    if ((int)blockIdx.x >= B) {
        // ---- fill CTA: linear float4 zero, RATE-LIMITED via __nanosleep ----
        // Each stripe-wave writes (gridDim.x-B)*1024 float4 (~1.9MB chip-wide)
        // then sleeps 1us -> ~30% duty, ~1.4TB/s aggregate, done in ~100us,
        // fully hidden under the ~128us scan without saturating DRAM.
        float4* o4 = reinterpret_cast<float4*>(out);
        const int n4     = B * T * (N_NEU / 4);
        const int nf     = gridDim.x - B;
        const int stride = nf * THREADS;
        for (int i = (blockIdx.x - B) * THREADS + tid; i < n4; i += stride) {
            o4[i] = make_float4(0.f, 0.f, 0.f, 0.f);
            __nanosleep(1000);
        }
        return;
    }

    // -------- scan CTA: one batch row; never touches `out` --------
    const int b = blockIdx.x;

    __shared__ int   s_idx[2][N_NEU];
    __shared__ float s_val[2][N_NEU];
    __shared__ int   s_cnt[2];
    __shared__ int   s_flag;
    __shared__ int   s_rc;
    if (tid < 2) s_cnt[tid] = 0;
    if (tid == 0) { s_flag = 0; s_rc = 0; }
    __syncthreads();

    float state = 0.0f;
    const float brec  = bias[tid];
    const float* wrow = W + (size_t)tid * N_NEU;
    const float* xb   = x + (size_t)b * T * N_NEU + tid;
    int*   rpos = g_pos[b];
    float* rval = g_val[b];

    // preload chunk 0 into buffer A (immediate offsets)
    float xA[CHUNK], xB[CHUNK];
#pragma unroll
    for (int s = 0; s < CHUNK; s++)
        xA[s] = xb[s * N_NEU];

    int pb = 0, qb = 1;

    // T must be a multiple of 2*CHUNK (1000 = 50 * 20)
    for (int tc = 0; tc < T; tc += 2 * CHUNK) {
        do_chunk(tc,         T, xA, xB, state, brec, wrow, xb, rpos, rval,
                 tid, s_idx, s_val, s_cnt, s_flag, s_rc, pb, qb);
        do_chunk(tc + CHUNK, T, xB, xA, state, brec, wrow, xb, rpos, rval,
                 tid, s_idx, s_val, s_cnt, s_flag, s_rc, pb, qb);
    }

    if (tid == 0) g_cnt[b] = min(s_rc, REC_CAP);
}

// One block per batch row: apply spike records, reset counter for replay.
__global__ void scatter_kernel(float* __restrict__ out, int T)
{
    const int c = blockIdx.x;
    const int n = g_cnt[c];
    for (int i = threadIdx.x; i < n; i += blockDim.x)
        out[(size_t)c * T * N_NEU + g_pos[c][i]] = g_val[c][i];
    __syncthreads();
    if (threadIdx.x == 0) g_cnt[c] = 0;
}

extern "C" void kernel_launch(void* const* d_in, const int* in_sizes, int n_in,
                              void* d_out, int out_size)
{
    const float* x    = (const float*)d_in[0];   // input_current [B, T, N]
    const float* W    = (const float*)d_in[1];   // w_rec [N, N]
    const float* bias = (const float*)d_in[2];   // b_rec [N]
    float* out = (float*)d_out;

    const int N = in_sizes[2];                   // 1024
    const int T = 1000;
    const int B = in_sizes[0] / (T * N);         // 32

    lif_merged_kernel<<<B + FILL_CTAS, THREADS>>>(x, W, bias, out, T, B);
    scatter_kernel<<<B, 256>>>(out, T);
}

// round 16
// speedup vs baseline: 1.4161x; 1.4161x over previous
#include <cuda_runtime.h>
#include <cuda_bf16.h>

// LIF recurrent scan, v13: merged scan + CTA-count-throttled fill + scatter.
//
// History: scan alone (store-free) = 128.5us on 32 SMs; output zeroing is
// 131MB. Full-rate fill (116 CTAs ~6TB/s) starves the scan (R14); nanosleep
// pacing blew up (R15). v13 throttles the fill STRUCTURALLY: 20 fill CTAs
// ~= 20 x 64GB/s ~= 1.25TB/s -> fill takes ~105us, hidden entirely under the
// ~128us scan, with combined traffic ~2.3TB/s << DRAM/LTS ceilings. No
// sleeps, no flags, no cross-CTA coupling of any kind.
//
// Scan core (proven v7+v11): 1 CTA/row, 1024 threads, 1 neuron/thread, state
// in registers for all T. CHUNK=10 speculative steps (no act, no stores, no
// barriers) + register fmaxf detector; mis-speculation -> exact replay with
// per-step barriers (rare). Next chunk's x prefetched into compile-time-bound
// registers (MLP=10). Scan never writes `out`: ~200 spikes total are appended
// to per-row __device__ record buffers (smem counter, snapshot/restore on
// rollback); a trailing 32-block scatter kernel applies them and resets the
// counters for graph replay.

#define N_NEU     1024
#define THREADS   1024
#define CHUNK     10          // even; T=1000 = 100 chunks
#define FILL_CTAS 20          // structural throttle: ~1.25 TB/s fill
#define MAX_B     32
#define REC_CAP   4096

__device__ int   g_cnt[MAX_B];
__device__ int   g_pos[MAX_B][REC_CAP];   // t*N + n
__device__ float g_val[MAX_B][REC_CAP];

__device__ __forceinline__ float rank_k(const int* __restrict__ idx,
                                        const float* __restrict__ val,
                                        int c, float rec,
                                        const float* __restrict__ wrow) {
    for (int k = 0; k < c; k++)
        rec = fmaf(val[k], wrow[idx[k]], rec);
    return rec;
}

__device__ __forceinline__ void do_chunk(
    int tc, int T,
    float (&xcur)[CHUNK], float (&xnxt)[CHUNK],   // compile-time bound: regs
    float& state, float brec,
    const float* __restrict__ wrow,
    const float* __restrict__ xb,
    int* __restrict__ rpos, float* __restrict__ rval,   // this row's records
    int tid,
    int (&s_idx)[2][N_NEU], float (&s_val)[2][N_NEU],
    int (&s_cnt)[2], int& s_flag, int& s_rc,
    int& pb, int& qb)
{
    const float ALPHA = 0.9f;
    const float OMA   = 1.0f - 0.9f;

    const int c_prev  = s_cnt[pb];     // uniform; stable since last barriers
    const int rc_snap = s_rc;

    // ---- prefetch next chunk: clamped base + immediate offsets (MLP=10) ----
    {
        const float* xp = xb + (size_t)min(tc + CHUNK, T - CHUNK) * N_NEU;
#pragma unroll
        for (int s = 0; s < CHUNK; s++)
            xnxt[s] = xp[s * N_NEU];
    }

    const float snap = state;
    float mx = 0.0f;

    // -------- fast speculative pass: no stores, no barriers, no act --------
#pragma unroll
    for (int s = 0; s < CHUNK - 1; s++) {
        float rec = brec;
        if (s == 0)                            // compile-time branch
            rec = rank_k(s_idx[pb], s_val[pb], c_prev, brec, wrow);

        mx = fmaxf(mx, state);                 // detector: 1 FMNMX/step

        const float tot = xcur[s] + rec;
        state = (state - 0.0f) * ALPHA + OMA * tot;
    }

    // ---- last step of chunk: exact act (its spikes feed the next chunk) ----
    {
        const float sv  = state;
        const float act = (sv > 0.0f) ? floorf(sv) : 0.0f;
        if (act != 0.0f) {                     // rare: list push + record
            const int p = atomicAdd(&s_cnt[qb], 1);
            s_idx[qb][p] = tid;
            s_val[qb][p] = act;
            const int r = atomicAdd(&s_rc, 1) & (REC_CAP - 1);
            rpos[r] = (tc + CHUNK - 1) * N_NEU + tid;
            rval[r] = act;
        }
        const float tot = xcur[CHUNK - 1] + brec;   // rec = bias for s > 0
        state = (sv - act) * ALPHA + OMA * tot;
    }

    if (mx >= 1.0f) s_flag = 1;                // one STS per chunk, rare

    __syncthreads();                    // B1: flag & pushes visible
    const int f = s_flag;
    if (tid == 0 && !f) s_cnt[pb] = 0;  // retire prev list (commit only)
    __syncthreads();                    // B2: flag consumed by all

    if (f) {
        // -------- rollback: exact replay with per-step barriers --------
        state = snap;
        if (tid == 0) { s_cnt[qb] = 0; s_flag = 0; s_rc = rc_snap; }
        __syncthreads();

        int rb = pb, wb = qb;
#pragma unroll 1
        for (int s = 0; s < CHUNK; s++) {
            const int c = s_cnt[rb];
            const float rec = rank_k(s_idx[rb], s_val[rb], c, brec, wrow);

            const float sv  = state;
            const float act = (sv > 0.0f) ? floorf(sv) : 0.0f;
            if (act != 0.0f) {
                const int p = atomicAdd(&s_cnt[wb], 1);
                s_idx[wb][p] = tid;
                s_val[wb][p] = act;
                const int r = atomicAdd(&s_rc, 1) & (REC_CAP - 1);
                rpos[r] = (tc + s) * N_NEU + tid;
                rval[r] = act;
            }

            const float tot = xcur[s] + rec;
            state = (sv - act) * ALPHA + OMA * tot;

            __syncthreads();
            if (tid == 0) s_cnt[rb] = 0;
            __syncthreads();
            const int tmp = rb; rb = wb; wb = tmp;
        }
        pb = rb; qb = wb;   // CHUNK even: last-step spikes in pb, qb zeroed
    } else {
        const int tmp = pb; pb = qb; qb = tmp;
    }
}

__global__ __launch_bounds__(THREADS, 1)
void lif_merged_kernel(const float* __restrict__ x,     // [B, T, N]
                       const float* __restrict__ W,     // [N, N] (out, in)
                       const float* __restrict__ bias,  // [N]
                       float* __restrict__ out,         // [B, T, N]
                       int T, int B)
{
    const int tid = threadIdx.x;

    if ((int)blockIdx.x >= B) {
        // ---- fill CTA: plain linear float4 zero; throttled by CTA COUNT ----
        float4* o4 = reinterpret_cast<float4*>(out);
        const int n4     = B * T * (N_NEU / 4);
        const int nf     = gridDim.x - B;
        const int stride = nf * THREADS;
        for (int i = (blockIdx.x - B) * THREADS + tid; i < n4; i += stride)
            o4[i] = make_float4(0.f, 0.f, 0.f, 0.f);
        return;
    }

    // -------- scan CTA: one batch row; never touches `out` --------
    const int b = blockIdx.x;

    __shared__ int   s_idx[2][N_NEU];
    __shared__ float s_val[2][N_NEU];
    __shared__ int   s_cnt[2];
    __shared__ int   s_flag;
    __shared__ int   s_rc;
    if (tid < 2) s_cnt[tid] = 0;
    if (tid == 0) { s_flag = 0; s_rc = 0; }
    __syncthreads();

    float state = 0.0f;
    const float brec  = bias[tid];
    const float* wrow = W + (size_t)tid * N_NEU;
    const float* xb   = x + (size_t)b * T * N_NEU + tid;
    int*   rpos = g_pos[b];
    float* rval = g_val[b];

    // preload chunk 0 into buffer A (immediate offsets)
    float xA[CHUNK], xB[CHUNK];
#pragma unroll
    for (int s = 0; s < CHUNK; s++)
        xA[s] = xb[s * N_NEU];

    int pb = 0, qb = 1;

    // T must be a multiple of 2*CHUNK (1000 = 50 * 20)
    for (int tc = 0; tc < T; tc += 2 * CHUNK) {
        do_chunk(tc,         T, xA, xB, state, brec, wrow, xb, rpos, rval,
                 tid, s_idx, s_val, s_cnt, s_flag, s_rc, pb, qb);
        do_chunk(tc + CHUNK, T, xB, xA, state, brec, wrow, xb, rpos, rval,
                 tid, s_idx, s_val, s_cnt, s_flag, s_rc, pb, qb);
    }

    if (tid == 0) g_cnt[b] = min(s_rc, REC_CAP);
}

// One block per batch row: apply spike records, reset counter for replay.
__global__ void scatter_kernel(float* __restrict__ out, int T)
{
    const int c = blockIdx.x;
    const int n = g_cnt[c];
    for (int i = threadIdx.x; i < n; i += blockDim.x)
        out[(size_t)c * T * N_NEU + g_pos[c][i]] = g_val[c][i];
    __syncthreads();
    if (threadIdx.x == 0) g_cnt[c] = 0;
}

extern "C" void kernel_launch(void* const* d_in, const int* in_sizes, int n_in,
                              void* d_out, int out_size)
{
    const float* x    = (const float*)d_in[0];   // input_current [B, T, N]
    const float* W    = (const float*)d_in[1];   // w_rec [N, N]
    const float* bias = (const float*)d_in[2];   // b_rec [N]
    float* out = (float*)d_out;

    const int N = in_sizes[2];                   // 1024
    const int T = 1000;
    const int B = in_sizes[0] / (T * N);         // 32

    lif_merged_kernel<<<B + FILL_CTAS, THREADS>>>(x, W, bias, out, T, B);
    scatter_kernel<<<B, 256>>>(out, T);
}